// round 1
// baseline (speedup 1.0000x reference)
#include <cuda_runtime.h>
#include <math.h>

// Scratch for per-batch modulated weights, layout [b][cin*9 + k][cout]
// 8 * 288 * 32 floats = 294,912 B
__device__ float g_wmod[8 * 288 * 32];

// ---------------------------------------------------------------------------
// Kernel 1: compute modulated + demodulated weights.
// grid = 8 (one block per batch), block = 256 (8 warps)
// ---------------------------------------------------------------------------
__global__ void modw_kernel(const float* __restrict__ style,
                            const float* __restrict__ weight,
                            const float* __restrict__ mod_w,
                            const float* __restrict__ mod_b)
{
    const int b    = blockIdx.x;
    const int tid  = threadIdx.x;
    const int warp = tid >> 5;
    const int lane = tid & 31;

    __shared__ float s_s[32];   // s[cin]

    const float mod_scale  = 1.0f / sqrtf(512.0f);
    const float conv_scale = 1.0f / sqrtf(288.0f);   // 1/sqrt(Cin*K*K)

    // --- s[cin] = style[b] . mod_w[cin] * mod_scale + mod_b[cin] ---
    #pragma unroll
    for (int i = 0; i < 4; i++) {
        int cin = warp + 8 * i;
        float acc = 0.f;
        const float* st = style + b * 512;
        const float* mw = mod_w + cin * 512;
        for (int j = lane; j < 512; j += 32)
            acc += st[j] * mw[j];
        #pragma unroll
        for (int off = 16; off; off >>= 1)
            acc += __shfl_xor_sync(0xffffffffu, acc, off);
        if (lane == 0)
            s_s[cin] = acc * mod_scale + mod_b[cin];
    }
    __syncthreads();

    // --- per-cout modulate + demodulate, write transposed layout ---
    #pragma unroll
    for (int i = 0; i < 4; i++) {
        int cout = warp + 8 * i;
        float vals[9];
        float ss = 0.f;
        #pragma unroll
        for (int j = 0; j < 9; j++) {
            int f   = lane + 32 * j;          // 0..287
            int cin = f / 9;
            int k   = f % 9;
            float v = conv_scale * weight[(cout * 32 + cin) * 9 + k] * s_s[cin];
            vals[j] = v;
            ss += v * v;
        }
        #pragma unroll
        for (int off = 16; off; off >>= 1)
            ss += __shfl_xor_sync(0xffffffffu, ss, off);
        float demod = rsqrtf(ss + 1e-8f);
        #pragma unroll
        for (int j = 0; j < 9; j++) {
            int f   = lane + 32 * j;
            g_wmod[(b * 288 + f) * 32 + cout] = vals[j] * demod;
        }
    }
}

// ---------------------------------------------------------------------------
// Kernel 2: direct conv, FFMA-bound.
// Tile: 64 (W) x 8 (H) output pixels per CTA, all 32 couts.
// block = 256 threads: 2 cout-groups of 16; within group 128 threads,
// each owning 4 consecutive x-pixels of one row.
// grid = (8 tilesX, 64 tilesY, 8 batch)
// ---------------------------------------------------------------------------
#define TW 64
#define TH 8
#define XS_W 68      // smem row stride (floats), 16B aligned
#define XS_H 10

__global__ __launch_bounds__(256, 1)
void conv_kernel(const float* __restrict__ x, float* __restrict__ out)
{
    extern __shared__ float smem[];
    float* sx = smem;                         // [32][10][68]
    float* sw = smem + 32 * XS_H * XS_W;      // [288][32]

    const int b   = blockIdx.z;
    const int tx0 = blockIdx.x * TW;
    const int ty0 = blockIdx.y * TH;
    const int tid = threadIdx.x;

    // ---- stage weights (9216 floats) ----
    {
        const float4* wsrc = (const float4*)(g_wmod + b * 288 * 32);
        float4* wdst = (float4*)sw;
        for (int i = tid; i < 288 * 32 / 4; i += 256)
            wdst[i] = wsrc[i];
    }

    // ---- stage input halo tile: 32 cin x 10 x 66 (zero-padded) ----
    {
        const float* xb = x + (size_t)b * 32 * 512 * 512;
        for (int i = tid; i < 32 * XS_H * 66; i += 256) {
            int cin = i / (XS_H * 66);
            int r   = i % (XS_H * 66);
            int ly  = r / 66;
            int lx  = r % 66;
            int gy  = ty0 - 1 + ly;
            int gx  = tx0 - 1 + lx;
            float v = 0.f;
            if ((unsigned)gy < 512u && (unsigned)gx < 512u)
                v = xb[(size_t)cin * 512 * 512 + gy * 512 + gx];
            sx[(cin * XS_H + ly) * XS_W + lx] = v;
        }
    }
    __syncthreads();

    const int cog = tid >> 7;          // cout group: 0 or 1
    const int t   = tid & 127;
    const int y   = t >> 4;            // 0..7
    const int x0  = (t & 15) << 2;     // 0..60, multiple of 4

    float acc[16][4];
    #pragma unroll
    for (int c = 0; c < 16; c++)
        #pragma unroll
        for (int p = 0; p < 4; p++)
            acc[c][p] = 0.f;

    const float* swg = sw + cog * 16;

    #pragma unroll 1
    for (int cin = 0; cin < 32; cin++) {
        const float* sxc = sx + (cin * XS_H + y) * XS_W + x0;
        #pragma unroll
        for (int ky = 0; ky < 3; ky++) {
            const float* row = sxc + ky * XS_W;
            float4 r03 = *(const float4*)row;        // halo lx = x0..x0+3
            float2 r45 = *(const float2*)(row + 4);  // halo lx = x0+4..x0+5
            float xr[6] = {r03.x, r03.y, r03.z, r03.w, r45.x, r45.y};
            #pragma unroll
            for (int kx = 0; kx < 3; kx++) {
                const float* wp = swg + (cin * 9 + ky * 3 + kx) * 32;
                float4 w0 = *(const float4*)(wp + 0);
                float4 w1 = *(const float4*)(wp + 4);
                float4 w2 = *(const float4*)(wp + 8);
                float4 w3 = *(const float4*)(wp + 12);
                float wv[16] = {w0.x, w0.y, w0.z, w0.w,
                                w1.x, w1.y, w1.z, w1.w,
                                w2.x, w2.y, w2.z, w2.w,
                                w3.x, w3.y, w3.z, w3.w};
                #pragma unroll
                for (int c = 0; c < 16; c++)
                    #pragma unroll
                    for (int p = 0; p < 4; p++)
                        acc[c][p] = fmaf(xr[kx + p], wv[c], acc[c][p]);
            }
        }
    }

    // ---- epilogue: coalesced float4 stores ----
    const int gy = ty0 + y;
    #pragma unroll
    for (int c = 0; c < 16; c++) {
        float4 v = make_float4(acc[c][0], acc[c][1], acc[c][2], acc[c][3]);
        size_t off = (((size_t)b * 32 + cog * 16 + c) * 512 + gy) * 512 + tx0 + x0;
        *(float4*)(out + off) = v;
    }
}

// ---------------------------------------------------------------------------
extern "C" void kernel_launch(void* const* d_in, const int* in_sizes, int n_in,
                              void* d_out, int out_size)
{
    const float* x      = (const float*)d_in[0];
    const float* style  = (const float*)d_in[1];
    const float* weight = (const float*)d_in[2];
    const float* mod_w  = (const float*)d_in[3];
    const float* mod_b  = (const float*)d_in[4];
    float* out = (float*)d_out;

    const int smem_bytes = (32 * XS_H * XS_W + 288 * 32) * sizeof(float); // 123,904
    cudaFuncSetAttribute(conv_kernel,
                         cudaFuncAttributeMaxDynamicSharedMemorySize, smem_bytes);

    modw_kernel<<<8, 256>>>(style, weight, mod_w, mod_b);

    dim3 grid(512 / TW, 512 / TH, 8);
    conv_kernel<<<grid, 256, smem_bytes>>>(x, out);
}